// round 16
// baseline (speedup 1.0000x reference)
#include <cuda_runtime.h>
#include <math.h>
#include <stdint.h>

// Problem constants
#define BB 4
#define SS 2048
#define NXC 1024
#define HH 16
#define DDC 64
#define PPC 512
#define TLEN (PPC + SS)                                                     // 2560
static const long long A_SIZE = (long long)BB * SS * NXC;                   // 8388608
static const long long PH     = (long long)BB * HH * TLEN * DDC;            // 10485760

// Scratch (allocation-free rule: __device__ globals)
__device__ float g_qkv[(size_t)BB * SS * 3 * NXC];       // 96 MB
__device__ float g_attn[(size_t)BB * SS * NXC];          // 32 MB
__device__ float g_present_fb[(size_t)2 * BB * HH * TLEN * DDC]; // 84 MB fallback
__device__ float g_kvr[(size_t)2 * BB * HH * TLEN * DDC];        // 84 MB (tf32-rounded KV)
__device__ float g_vtr[(size_t)BB * HH * DDC * TLEN];    // 42 MB (V^T, tf32, [b][h][d][t])
__device__ float g_xr[(size_t)BB * SS * NXC];            // 32 MB  (x rounded to tf32)
__device__ float g_wqkvt[(size_t)3 * NXC * NXC];         // 12 MB (W^T, tf32, [N][K])
__device__ float g_wprojt[(size_t)NXC * NXC];            // 4 MB  (W^T, tf32, [N][K])

__device__ __forceinline__ uint32_t f2tf32(float x) {
    uint32_t r;
    asm("cvt.rna.tf32.f32 %0, %1;" : "=r"(r) : "f"(x));
    return r;
}
__device__ __forceinline__ float ex2f(float x) {
    float r;
    asm("ex2.approx.f32 %0, %1;" : "=f"(r) : "f"(x));
    return r;
}
__device__ __forceinline__ float rcpf(float x) {
    float r;
    asm("rcp.approx.f32 %0, %1;" : "=f"(r) : "f"(x));
    return r;
}

#define MMA_TF32(d, a, b) \
    asm volatile("mma.sync.aligned.m16n8k8.row.col.f32.tf32.tf32.f32 " \
        "{%0,%1,%2,%3}, {%4,%5,%6,%7}, {%8,%9}, {%0,%1,%2,%3};" \
        : "+f"((d)[0]), "+f"((d)[1]), "+f"((d)[2]), "+f"((d)[3]) \
        : "r"((a)[0]), "r"((a)[1]), "r"((a)[2]), "r"((a)[3]), \
          "r"((b)[0]), "r"((b)[1]))

__device__ __forceinline__ void ldm_x4(uint32_t* r, uint32_t addr) {
    asm volatile("ldmatrix.sync.aligned.m8n8.x4.shared.b16 {%0,%1,%2,%3}, [%4];"
                 : "=r"(r[0]), "=r"(r[1]), "=r"(r[2]), "=r"(r[3]) : "r"(addr));
}

__device__ __forceinline__ void cp_async16(uint32_t dst, const void* src) {
    asm volatile("cp.async.cg.shared.global [%0], [%1], 16;" :: "r"(dst), "l"(src));
}
#define CP_COMMIT() asm volatile("cp.async.commit_group;" ::: "memory")
#define CP_WAIT1()  asm volatile("cp.async.wait_group 1;" ::: "memory")
#define CP_WAIT0()  asm volatile("cp.async.wait_group 0;" ::: "memory")

// ---------------------------------------------------------------------------
// Elementwise tf32 rounding (rna)
// ---------------------------------------------------------------------------
__global__ __launch_bounds__(256)
void round_tf32_kernel(const float* __restrict__ src, float* __restrict__ dst)
{
    const size_t i = (size_t)blockIdx.x * 256 + threadIdx.x;
    float4 v = ((const float4*)src)[i];
    ((uint4*)dst)[i] = make_uint4(f2tf32(v.x), f2tf32(v.y), f2tf32(v.z), f2tf32(v.w));
}

// ---------------------------------------------------------------------------
// Transpose + tf32 round: src[R][C] -> dst[C][R]
// ---------------------------------------------------------------------------
__global__ __launch_bounds__(256)
void trans_round_kernel(const float* __restrict__ src, float* __restrict__ dst,
                        int R, int C)
{
    __shared__ float tile[32][33];
    const int bx = blockIdx.x * 32;
    const int by = blockIdx.y * 32;
    const int tx = threadIdx.x & 31, ty = threadIdx.x >> 5;
    #pragma unroll
    for (int i = 0; i < 32; i += 8)
        tile[ty + i][tx] = src[(size_t)(by + ty + i) * C + bx + tx];
    __syncthreads();
    #pragma unroll
    for (int i = 0; i < 32; i += 8)
        dst[(size_t)(bx + ty + i) * R + by + tx] =
            __uint_as_float(f2tf32(tile[tx][ty + i]));
}

// ---------------------------------------------------------------------------
// Per-head V transpose: kvr V part [b][h][t][d] -> vtr [b][h][d][t]
// (already tf32; tiled, fully coalesced)
// ---------------------------------------------------------------------------
__global__ __launch_bounds__(256)
void vtrans_kernel(const float* __restrict__ kvr, float* __restrict__ vtr)
{
    __shared__ float tile[32][33];
    const int t0 = blockIdx.x * 32;
    const int d0 = blockIdx.y * 32;
    const int bh = blockIdx.z;
    const float* src = kvr + PH + (size_t)bh * TLEN * DDC;
    float* dst = vtr + (size_t)bh * DDC * TLEN;
    const int tx = threadIdx.x & 31, ty = threadIdx.x >> 5;
    #pragma unroll
    for (int i = 0; i < 32; i += 8)
        tile[ty + i][tx] = src[(size_t)(t0 + ty + i) * DDC + d0 + tx];
    __syncthreads();
    #pragma unroll
    for (int i = 0; i < 32; i += 8)
        dst[(size_t)(d0 + ty + i) * TLEN + t0 + tx] = tile[tx][ty + i];
}

// ---------------------------------------------------------------------------
// tf32 tensor-core GEMM (R12 version: 256 thr, 8 warps 2x4, 2 CTAs/SM)
// ---------------------------------------------------------------------------
#define TS 36
#define STAGE_FLOATS (256 * TS)
#define STAGE_BYTES  (STAGE_FLOATS * 4)
#define GEMM_SMEM    (3 * STAGE_BYTES)

__global__ __launch_bounds__(256, 2)
void gemm_tf32_kernel(const float* __restrict__ A, const float* __restrict__ Bt,
                      const float* __restrict__ bias, float* __restrict__ C,
                      int M, int N, int K)
{
    extern __shared__ float smf[];
    uint32_t sm_base;
    asm("{ .reg .u64 t; cvta.to.shared.u64 t, %1; cvt.u32.u64 %0, t; }"
        : "=r"(sm_base) : "l"(smf));

    const int tid = threadIdx.x;
    const int wid = tid >> 5, lane = tid & 31;
    const int g = lane >> 2, t = lane & 3;
    const int warpM = wid & 1, warpN = wid >> 1;
    const int lm = lane >> 3, lr = lane & 7;

    const float* Ab = A + (size_t)(blockIdx.y * 128) * K;
    const float* Bb = Bt + (size_t)(blockIdx.x * 128) * K;

    int rowu[4], colu[4];
    #pragma unroll
    for (int u = 0; u < 4; u++) {
        int idx = tid + u * 256;
        rowu[u] = idx >> 3;  colu[u] = (idx & 7) * 4;
    }
    uint32_t a_dst[4], b_dst[4];
    #pragma unroll
    for (int u = 0; u < 4; u++) {
        a_dst[u] = (rowu[u] * TS + colu[u]) * 4;
        b_dst[u] = ((128 + rowu[u]) * TS + colu[u]) * 4;
    }

    const uint32_t aoff = (uint32_t)((((lm & 1) * 8 + lr) * TS + (lm >> 1) * 4) * 4);
    const uint32_t boff = (uint32_t)((((lm >> 1) * 8 + lr) * TS + (lm & 1) * 4) * 4);
    const uint32_t a_base0 = (uint32_t)(warpM * 64 * TS * 4) + aoff;
    const uint32_t b_base0 = (uint32_t)((128 + warpN * 32) * TS * 4) + boff;

    float acc[4][4][4];
    #pragma unroll
    for (int mi = 0; mi < 4; mi++)
        #pragma unroll
        for (int ni = 0; ni < 4; ni++)
            #pragma unroll
            for (int e = 0; e < 4; e++) acc[mi][ni][e] = 0.f;

    const int ktiles = K >> 5;

    auto issue = [&](int kt, int s) {
        const int k0 = kt << 5;
        const uint32_t sb = sm_base + s * STAGE_BYTES;
        #pragma unroll
        for (int u = 0; u < 4; u++)
            cp_async16(sb + a_dst[u], Ab + (size_t)rowu[u] * K + k0 + colu[u]);
        #pragma unroll
        for (int u = 0; u < 4; u++)
            cp_async16(sb + b_dst[u], Bb + (size_t)rowu[u] * K + k0 + colu[u]);
    };

    issue(0, 0); CP_COMMIT();
    issue(1, 1); CP_COMMIT();

    int s_cur = 0;
    for (int kt = 0; kt < ktiles; kt++) {
        CP_WAIT1();
        __syncthreads();

        if (kt + 2 < ktiles) {
            int s_next = s_cur + 2; if (s_next >= 3) s_next -= 3;
            issue(kt + 2, s_next);
        }
        CP_COMMIT();

        const uint32_t aA = sm_base + s_cur * STAGE_BYTES + a_base0;
        const uint32_t aB = sm_base + s_cur * STAGE_BYTES + b_base0;
        #pragma unroll
        for (int ks = 0; ks < 4; ks++) {
            const uint32_t kb4 = ks * 8 * 4;
            uint32_t af[4][4], bf[4][2];
            #pragma unroll
            for (int mi = 0; mi < 4; mi++)
                ldm_x4(af[mi], aA + mi * (16 * TS * 4) + kb4);
            #pragma unroll
            for (int np = 0; np < 2; np++) {
                uint32_t tmp[4];
                ldm_x4(tmp, aB + np * (16 * TS * 4) + kb4);
                bf[np * 2][0] = tmp[0];     bf[np * 2][1] = tmp[1];
                bf[np * 2 + 1][0] = tmp[2]; bf[np * 2 + 1][1] = tmp[3];
            }
            #pragma unroll
            for (int mi = 0; mi < 4; mi++)
                #pragma unroll
                for (int ni = 0; ni < 4; ni++)
                    MMA_TF32(acc[mi][ni], af[mi], bf[ni]);
        }

        s_cur++; if (s_cur >= 3) s_cur = 0;
    }

    #pragma unroll
    for (int mi = 0; mi < 4; mi++) {
        const int row = blockIdx.y * 128 + warpM * 64 + mi * 16 + g;
        #pragma unroll
        for (int ni = 0; ni < 4; ni++) {
            const int col = blockIdx.x * 128 + warpN * 32 + ni * 8 + t * 2;
            const float b0 = bias[col], b1 = bias[col + 1];
            float2 v0 = make_float2(acc[mi][ni][0] + b0, acc[mi][ni][1] + b1);
            float2 v1 = make_float2(acc[mi][ni][2] + b0, acc[mi][ni][3] + b1);
            *(float2*)(C + (size_t)row * N + col)       = v0;
            *(float2*)(C + (size_t)(row + 8) * N + col) = v1;
        }
    }
}

// ---------------------------------------------------------------------------
// present = concat(past, new kv): exact to d_out AND tf32-rounded to g_kvr
// ---------------------------------------------------------------------------
__global__ __launch_bounds__(256)
void build_present_kernel(const float* __restrict__ past, float* __restrict__ present,
                          float* __restrict__ kvr)
{
    const long long TOTAL4 = 2LL * BB * HH * TLEN * DDC / 4;
    long long i = (long long)blockIdx.x * blockDim.x + threadIdx.x;
    if (i >= TOTAL4) return;
    int d4 = (int)(i & 15);
    long long r = i >> 4;
    int t  = (int)(r % TLEN); r /= TLEN;
    int h  = (int)(r % HH); r /= HH;
    int b  = (int)(r % BB); r /= BB;
    int kv = (int)r;
    float4 v;
    if (t < PPC) {
        long long src = ((((long long)kv * BB + b) * HH + h) * PPC + t) * (DDC / 4) + d4;
        v = ((const float4*)past)[src];
    } else {
        int s = t - PPC;
        long long src = (((long long)b * SS + s) * (3 * NXC) + (kv + 1) * NXC + h * DDC) / 4 + d4;
        v = ((const float4*)g_qkv)[src];
    }
    ((float4*)present)[i] = v;
    ((uint4*)kvr)[i] = make_uint4(f2tf32(v.x), f2tf32(v.y), f2tf32(v.z), f2tf32(v.w));
}

// ---------------------------------------------------------------------------
// Flash attention (R15 structure): 64q/CTA, 128 thr, 2 CTAs/SM, no-max
// softmax (MUFU ex2), LPT, warp-private P, 1 barrier/tile.
// THIS ROUND: PV B-operand from transposed V (g_vtr) via ldmatrix —
// replaces 64 scalar V LDS per warp per tile with 16 ldmatrix. NO Q-hoist
// (deconfounds R14's regression).
// ---------------------------------------------------------------------------
#define Q_OFF 0          // 64*68  = 4352
#define K_OFF 4352       // 2*64*68 = 8704
#define V_OFF 13056      // 2*64*68 = 8704 (Vt tiles: 64 d-rows x 64 tokens)
#define P_OFF 21760      // 4 warps * 32*36 = 4608
#define SX_OFF 26368     // 128
#define ATTN_SMEM (26496 * 4)   // 105984 bytes -> 2 CTAs/SM

__global__ __launch_bounds__(128, 2)
void attn_mma_kernel(const float* __restrict__ kvr, const float* __restrict__ vtr)
{
    extern __shared__ float smf[];
    uint32_t sm_base;
    asm("{ .reg .u64 t; cvta.to.shared.u64 t, %1; cvt.u32.u64 %0, t; }"
        : "=r"(sm_base) : "l"(smf));

    const int qb = gridDim.x - 1 - blockIdx.x;   // LPT: biggest jobs first
    const int h = blockIdx.y, b = blockIdx.z;
    const int tid = threadIdx.x, wid = tid >> 5, lane = tid & 31;
    const int g = lane >> 2, t = lane & 3;
    const int wq = wid >> 1, wk = wid & 1;
    const int rA = wq * 32 + g;
    const int lm = lane >> 3, lr = lane & 7;

    const float* Kb = kvr + (size_t)(b * HH + h) * TLEN * DDC;
    const float* Vtb = vtr + (size_t)(b * HH + h) * DDC * TLEN;

    const float SC = 0.125f * 1.4426950408889634f;
    const int lrow = tid >> 4, lc4 = (tid & 15) << 2;
    {
        const float* src = g_qkv + ((size_t)(b * SS + qb * 64 + lrow)) * (3 * NXC)
                         + h * DDC + lc4;
        float* dq = smf + Q_OFF + lrow * 68 + lc4;
        #pragma unroll
        for (int u = 0; u < 8; u++) {
            float4 v = *(const float4*)(src + (size_t)u * 8 * (3 * NXC));
            *(uint4*)(dq + u * 8 * 68) =
                make_uint4(f2tf32(v.x * SC), f2tf32(v.y * SC),
                           f2tf32(v.z * SC), f2tf32(v.w * SC));
        }
    }

    // ldmatrix lane offsets
    const uint32_t aoff68 = (uint32_t)((((lm & 1) * 8 + lr) * 68 + (lm >> 1) * 4) * 4);
    const uint32_t aoff36 = (uint32_t)((((lm & 1) * 8 + lr) * 36 + (lm >> 1) * 4) * 4);
    const uint32_t boff68 = (uint32_t)((((lm >> 1) * 8 + lr) * 68 + (lm & 1) * 4) * 4);

    const uint32_t aQ  = sm_base + Q_OFF * 4 + (uint32_t)(wq * 32 * 68 * 4) + aoff68;
    const uint32_t aP  = sm_base + P_OFF * 4 + (uint32_t)(wid * 1152 * 4) + aoff36;
    const uint32_t bK0 = sm_base + K_OFF * 4 + (uint32_t)(wk * 32 * 68 * 4) + boff68;
    const uint32_t bV0 = sm_base + V_OFF * 4 + boff68;
    float* Pw = smf + P_OFF + wid * 1152;   // warp-private 32x36

    float o[2][8][4];
    #pragma unroll
    for (int mi = 0; mi < 2; mi++)
        #pragma unroll
        for (int ni = 0; ni < 8; ni++)
            #pragma unroll
            for (int e = 0; e < 4; e++) o[mi][ni][e] = 0.f;
    float l[2][2] = {{0.f, 0.f}, {0.f, 0.f}};

    // cp.async: K tile [token][d] stride 68; Vt tile [d][token] stride 68
    const uint32_t kdst0 = sm_base + (K_OFF + lrow * 68 + lc4) * 4;
    const uint32_t vdst0 = sm_base + (V_OFF + lrow * 68 + lc4) * 4;
    const float* ksrc0 = Kb + lrow * DDC + lc4;
    const float* vtsrc0 = Vtb + (size_t)lrow * TLEN + lc4;

    auto issue = [&](int kt, int s) {
        const size_t koff = (size_t)kt * 64 * DDC;
        const int toff = kt * 64;
        const uint32_t kd = kdst0 + s * 4352 * 4;
        const uint32_t vd = vdst0 + s * 4352 * 4;
        #pragma unroll
        for (int u = 0; u < 8; u++) {
            cp_async16(kd + u * 8 * 68 * 4, ksrc0 + koff + u * 8 * DDC);
            cp_async16(vd + u * 8 * 68 * 4, vtsrc0 + toff + (size_t)u * 8 * TLEN);
        }
    };

    const int ntiles = qb + 9;
    issue(0, 0); CP_COMMIT();

    for (int kt = 0; kt < ntiles; kt++) {
        CP_WAIT0();
        __syncthreads();   // KV(kt) ready; all warps past tile kt-1 buffers
        if (kt + 1 < ntiles) { issue(kt + 1, (kt + 1) & 1); CP_COMMIT(); }

        const uint32_t bK = bK0 + (uint32_t)((kt & 1) * 4352 * 4);
        const uint32_t bV = bV0 + (uint32_t)((kt & 1) * 4352 * 4);

        // ---- S quadrant = Q[wq rows 32] @ K^T[wk keys 32] ----
        float s[2][4][4];
        #pragma unroll
        for (int mi = 0; mi < 2; mi++)
            #pragma unroll
            for (int ni = 0; ni < 4; ni++)
                #pragma unroll
                for (int e = 0; e < 4; e++) s[mi][ni][e] = 0.f;

        #pragma unroll
        for (int ks = 0; ks < 8; ks++) {
            const uint32_t kb4 = ks * 8 * 4;
            uint32_t af[2][4], bf[4][2];
            #pragma unroll
            for (int mi = 0; mi < 2; mi++)
                ldm_x4(af[mi], aQ + mi * (16 * 68 * 4) + kb4);
            #pragma unroll
            for (int np = 0; np < 2; np++) {
                uint32_t tmp[4];
                ldm_x4(tmp, bK + np * (16 * 68 * 4) + kb4);
                bf[np * 2][0] = tmp[0];     bf[np * 2][1] = tmp[1];
                bf[np * 2 + 1][0] = tmp[2]; bf[np * 2 + 1][1] = tmp[3];
            }
            #pragma unroll
            for (int mi = 0; mi < 2; mi++)
                #pragma unroll
                for (int ni = 0; ni < 4; ni++)
                    MMA_TF32(s[mi][ni], af[mi], bf[ni]);
        }

        if (kt == ntiles - 1) {   // diagonal tile: mask key col > query row
            #pragma unroll
            for (int mi = 0; mi < 2; mi++) {
                const int r = rA + mi * 16;
                #pragma unroll
                for (int ni = 0; ni < 4; ni++) {
                    const int c = wk * 32 + ni * 8 + 2 * t;
                    if (c     > r)     s[mi][ni][0] = -1e30f;
                    if (c + 1 > r)     s[mi][ni][1] = -1e30f;
                    if (c     > r + 8) s[mi][ni][2] = -1e30f;
                    if (c + 1 > r + 8) s[mi][ni][3] = -1e30f;
                }
            }
        }

        // ---- exp2 via MUFU (no max), accumulate l, write warp-private P ----
        #pragma unroll
        for (int mi = 0; mi < 2; mi++) {
            const int rl = g + mi * 16;
            #pragma unroll
            for (int ni = 0; ni < 4; ni++) {
                const float e0 = ex2f(s[mi][ni][0]);
                const float e1 = ex2f(s[mi][ni][1]);
                const float e2 = ex2f(s[mi][ni][2]);
                const float e3 = ex2f(s[mi][ni][3]);
                l[mi][0] += e0 + e1;
                l[mi][1] += e2 + e3;
                const int c = ni * 8 + 2 * t;
                *(uint2*)&Pw[rl * 36 + c]       = make_uint2(f2tf32(e0), f2tf32(e1));
                *(uint2*)&Pw[(rl + 8) * 36 + c] = make_uint2(f2tf32(e2), f2tf32(e3));
            }
        }
        __syncwarp();   // warp-private P: order STS->ldmatrix

        // ---- O += P[own 32 keys] @ Vt[all 64 d][those keys] (ldmatrix) ----
        #pragma unroll
        for (int ks = 0; ks < 4; ks++) {
            const uint32_t tok4 = (uint32_t)((wk * 32 + ks * 8) * 4);
            uint32_t af[2][4], bf[8][2];
            #pragma unroll
            for (int mi = 0; mi < 2; mi++)
                ldm_x4(af[mi], aP + mi * (16 * 36 * 4) + ks * 8 * 4);
            #pragma unroll
            for (int np = 0; np < 4; np++) {
                uint32_t tmp[4];
                ldm_x4(tmp, bV + np * (16 * 68 * 4) + tok4);
                bf[np * 2][0] = tmp[0];     bf[np * 2][1] = tmp[1];
                bf[np * 2 + 1][0] = tmp[2]; bf[np * 2 + 1][1] = tmp[3];
            }
            #pragma unroll
            for (int mi = 0; mi < 2; mi++)
                #pragma unroll
                for (int ni = 0; ni < 8; ni++)
                    MMA_TF32(o[mi][ni], af[mi], bf[ni]);
        }
    }

    // ---- l reduction (4 t-lanes), publish per-wk sums ----
    float* Sx = smf + SX_OFF;   // [2 wk][64 rows]
    #pragma unroll
    for (int mi = 0; mi < 2; mi++)
        #pragma unroll
        for (int hh = 0; hh < 2; hh++) {
            float v = l[mi][hh];
            v += __shfl_xor_sync(0xffffffffu, v, 1);
            v += __shfl_xor_sync(0xffffffffu, v, 2);
            l[mi][hh] = v;
        }
    if (t == 0) {
        #pragma unroll
        for (int mi = 0; mi < 2; mi++) {
            Sx[wk * 64 + rA + mi * 16]     = l[mi][0];
            Sx[wk * 64 + rA + mi * 16 + 8] = l[mi][1];
        }
    }

    // ---- O exchange: wk=1 publishes partials; wk=0 combines + stores ----
    float* Ox = smf + K_OFF;   // reuse K region (64 rows x stride 68)
    if (wk == 1) {
        #pragma unroll
        for (int mi = 0; mi < 2; mi++) {
            const int r = rA + mi * 16;
            #pragma unroll
            for (int ni = 0; ni < 8; ni++) {
                const int c = ni * 8 + 2 * t;
                *(float2*)&Ox[r * 68 + c]       = make_float2(o[mi][ni][0], o[mi][ni][1]);
                *(float2*)&Ox[(r + 8) * 68 + c] = make_float2(o[mi][ni][2], o[mi][ni][3]);
            }
        }
    }
    __syncthreads();

    if (wk == 0) {
        #pragma unroll
        for (int mi = 0; mi < 2; mi++) {
            const int row0 = rA + mi * 16;
            const float inv0 = rcpf(Sx[row0] + Sx[64 + row0]);
            const float inv1 = rcpf(Sx[row0 + 8] + Sx[64 + row0 + 8]);
            const int srow = qb * 64 + row0;
            float* dst0 = g_attn + ((size_t)(b * SS + srow)) * NXC + h * DDC;
            float* dst1 = dst0 + (size_t)8 * NXC;
            #pragma unroll
            for (int ni = 0; ni < 8; ni++) {
                const int c = ni * 8 + 2 * t;
                float2 p0 = *(float2*)&Ox[row0 * 68 + c];
                float2 p1 = *(float2*)&Ox[(row0 + 8) * 68 + c];
                *(uint2*)(dst0 + c) = make_uint2(f2tf32((o[mi][ni][0] + p0.x) * inv0),
                                                 f2tf32((o[mi][ni][1] + p0.y) * inv0));
                *(uint2*)(dst1 + c) = make_uint2(f2tf32((o[mi][ni][2] + p1.x) * inv1),
                                                 f2tf32((o[mi][ni][3] + p1.y) * inv1));
            }
        }
    }
}

// ---------------------------------------------------------------------------
extern "C" void kernel_launch(void* const* d_in, const int* in_sizes, int n_in,
                              void* d_out, int out_size)
{
    const float* x     = (const float*)d_in[0];
    const float* past  = (const float*)d_in[1];
    const float* wqkv  = (const float*)d_in[2];
    const float* bqkv  = (const float*)d_in[3];
    const float* wproj = (const float*)d_in[4];
    const float* bproj = (const float*)d_in[5];
    float* out = (float*)d_out;

    float *qkv, *attn, *kvr, *vtr, *xr, *wqkvt, *wprojt;
    cudaGetSymbolAddress((void**)&qkv, g_qkv);
    cudaGetSymbolAddress((void**)&attn, g_attn);
    cudaGetSymbolAddress((void**)&kvr, g_kvr);
    cudaGetSymbolAddress((void**)&vtr, g_vtr);
    cudaGetSymbolAddress((void**)&xr, g_xr);
    cudaGetSymbolAddress((void**)&wqkvt, g_wqkvt);
    cudaGetSymbolAddress((void**)&wprojt, g_wprojt);

    float* present = nullptr;
    if ((long long)out_size >= A_SIZE + 2 * PH) {
        present = out + A_SIZE;
    } else {
        cudaGetSymbolAddress((void**)&present, g_present_fb);
    }

    cudaFuncSetAttribute(gemm_tf32_kernel,
                         cudaFuncAttributeMaxDynamicSharedMemorySize, GEMM_SMEM);
    cudaFuncSetAttribute(attn_mma_kernel,
                         cudaFuncAttributeMaxDynamicSharedMemorySize, ATTN_SMEM);

    // 0) pre-round x; transpose+round weights to [N][K]
    round_tf32_kernel<<<(int)(A_SIZE / 4 / 256), 256>>>(x, xr);
    trans_round_kernel<<<dim3(3 * NXC / 32, NXC / 32), 256>>>(wqkv, wqkvt, NXC, 3 * NXC);
    trans_round_kernel<<<dim3(NXC / 32, NXC / 32), 256>>>(wproj, wprojt, NXC, NXC);

    // 1) QKV GEMM
    gemm_tf32_kernel<<<dim3(3 * NXC / 128, BB * SS / 128), 256, GEMM_SMEM>>>(
        xr, wqkvt, bqkv, qkv, BB * SS, 3 * NXC, NXC);

    // 2) present (exact) + rounded KV copy; then V transpose
    {
        long long tot4 = 2LL * BB * HH * TLEN * DDC / 4;
        build_present_kernel<<<(int)((tot4 + 255) / 256), 256>>>(past, present, kvr);
    }
    vtrans_kernel<<<dim3(TLEN / 32, DDC / 32, BB * HH), 256>>>(kvr, vtr);

    // 3) flash attention (Vt-ldmatrix PV, warp-private P, MUFU exp)
    attn_mma_kernel<<<dim3(SS / 64, HH, BB), 128, ATTN_SMEM>>>(kvr, vtr);

    // 4) output projection
    gemm_tf32_kernel<<<dim3(NXC / 128, BB * SS / 128), 256, GEMM_SMEM>>>(
        attn, wprojt, bproj, out, BB * SS, NXC, NXC);
}

// round 17
// speedup vs baseline: 1.6315x; 1.6315x over previous
#include <cuda_runtime.h>
#include <math.h>
#include <stdint.h>

// Problem constants
#define BB 4
#define SS 2048
#define NXC 1024
#define HH 16
#define DDC 64
#define PPC 512
#define TLEN (PPC + SS)                                                     // 2560
static const long long A_SIZE = (long long)BB * SS * NXC;                   // 8388608
static const long long PH     = (long long)BB * HH * TLEN * DDC;            // 10485760

// Scratch (allocation-free rule: __device__ globals)
__device__ float g_qr[(size_t)BB * SS * NXC];            // 32 MB (Q scaled+tf32, packed)
__device__ float g_attn[(size_t)BB * SS * NXC];          // 32 MB
__device__ float g_present_fb[(size_t)2 * BB * HH * TLEN * DDC]; // 84 MB fallback
__device__ float g_kvr[(size_t)2 * BB * HH * TLEN * DDC];        // 84 MB (tf32 KV)
__device__ float g_xr[(size_t)BB * SS * NXC];            // 32 MB (x rounded to tf32)
__device__ float g_wqkvt[(size_t)3 * NXC * NXC];         // 12 MB (W^T, tf32, [N][K])
__device__ float g_wprojt[(size_t)NXC * NXC];            // 4 MB  (W^T, tf32, [N][K])

__device__ __forceinline__ uint32_t f2tf32(float x) {
    uint32_t r;
    asm("cvt.rna.tf32.f32 %0, %1;" : "=r"(r) : "f"(x));
    return r;
}
__device__ __forceinline__ float ex2f(float x) {
    float r;
    asm("ex2.approx.f32 %0, %1;" : "=f"(r) : "f"(x));
    return r;
}
__device__ __forceinline__ float rcpf(float x) {
    float r;
    asm("rcp.approx.f32 %0, %1;" : "=f"(r) : "f"(x));
    return r;
}

#define MMA_TF32(d, a, b) \
    asm volatile("mma.sync.aligned.m16n8k8.row.col.f32.tf32.tf32.f32 " \
        "{%0,%1,%2,%3}, {%4,%5,%6,%7}, {%8,%9}, {%0,%1,%2,%3};" \
        : "+f"((d)[0]), "+f"((d)[1]), "+f"((d)[2]), "+f"((d)[3]) \
        : "r"((a)[0]), "r"((a)[1]), "r"((a)[2]), "r"((a)[3]), \
          "r"((b)[0]), "r"((b)[1]))

__device__ __forceinline__ void ldm_x4(uint32_t* r, uint32_t addr) {
    asm volatile("ldmatrix.sync.aligned.m8n8.x4.shared.b16 {%0,%1,%2,%3}, [%4];"
                 : "=r"(r[0]), "=r"(r[1]), "=r"(r[2]), "=r"(r[3]) : "r"(addr));
}

__device__ __forceinline__ void cp_async16(uint32_t dst, const void* src) {
    asm volatile("cp.async.cg.shared.global [%0], [%1], 16;" :: "r"(dst), "l"(src));
}
#define CP_COMMIT() asm volatile("cp.async.commit_group;" ::: "memory")
#define CP_WAIT1()  asm volatile("cp.async.wait_group 1;" ::: "memory")
#define CP_WAIT0()  asm volatile("cp.async.wait_group 0;" ::: "memory")

// ---------------------------------------------------------------------------
// Elementwise tf32 rounding (rna)
// ---------------------------------------------------------------------------
__global__ __launch_bounds__(256)
void round_tf32_kernel(const float* __restrict__ src, float* __restrict__ dst)
{
    const size_t i = (size_t)blockIdx.x * 256 + threadIdx.x;
    float4 v = ((const float4*)src)[i];
    ((uint4*)dst)[i] = make_uint4(f2tf32(v.x), f2tf32(v.y), f2tf32(v.z), f2tf32(v.w));
}

// ---------------------------------------------------------------------------
// Transpose + tf32 round: src[R][C] -> dst[C][R]
// ---------------------------------------------------------------------------
__global__ __launch_bounds__(256)
void trans_round_kernel(const float* __restrict__ src, float* __restrict__ dst,
                        int R, int C)
{
    __shared__ float tile[32][33];
    const int bx = blockIdx.x * 32;
    const int by = blockIdx.y * 32;
    const int tx = threadIdx.x & 31, ty = threadIdx.x >> 5;
    #pragma unroll
    for (int i = 0; i < 32; i += 8)
        tile[ty + i][tx] = src[(size_t)(by + ty + i) * C + bx + tx];
    __syncthreads();
    #pragma unroll
    for (int i = 0; i < 32; i += 8)
        dst[(size_t)(bx + ty + i) * R + by + tx] =
            __uint_as_float(f2tf32(tile[tx][ty + i]));
}

// ---------------------------------------------------------------------------
// Copy past KV into present (exact) + kvr (tf32). New-token KV is written
// directly by the QKV GEMM epilogue.
// ---------------------------------------------------------------------------
__global__ __launch_bounds__(256)
void build_past_kernel(const float* __restrict__ past, float* __restrict__ present,
                       float* __restrict__ kvr)
{
    const int PER = PPC * DDC / 4;   // float4 per (kv,b,h) group
    const long long TOTAL = 2LL * BB * HH * PER;
    long long i = (long long)blockIdx.x * 256 + threadIdx.x;
    if (i >= TOTAL) return;
    const int grp = (int)(i / PER), off = (int)(i % PER);
    float4 v = ((const float4*)past)[i];
    const size_t dsto = (size_t)grp * (TLEN * DDC / 4) + off;
    ((float4*)present)[dsto] = v;
    ((uint4*)kvr)[dsto] = make_uint4(f2tf32(v.x), f2tf32(v.y), f2tf32(v.z), f2tf32(v.w));
}

// ---------------------------------------------------------------------------
// tf32 tensor-core GEMM (R12/R15 core). mode 0: C = A@Bt^T + bias (proj).
// mode 1 (QKV): epilogue scatters Q (scaled+tf32) into C(=qr) and K/V into
// present (fp32 exact) + kvr (tf32) at final head-major addresses.
// ---------------------------------------------------------------------------
#define TS 36
#define STAGE_FLOATS (256 * TS)
#define STAGE_BYTES  (STAGE_FLOATS * 4)
#define GEMM_SMEM    (3 * STAGE_BYTES)

__global__ __launch_bounds__(256, 2)
void gemm_tf32_kernel(const float* __restrict__ A, const float* __restrict__ Bt,
                      const float* __restrict__ bias, float* __restrict__ C,
                      int M, int N, int K, int mode,
                      float* __restrict__ present, float* __restrict__ kvr)
{
    extern __shared__ float smf[];
    uint32_t sm_base;
    asm("{ .reg .u64 t; cvta.to.shared.u64 t, %1; cvt.u32.u64 %0, t; }"
        : "=r"(sm_base) : "l"(smf));

    const int tid = threadIdx.x;
    const int wid = tid >> 5, lane = tid & 31;
    const int g = lane >> 2, t = lane & 3;
    const int warpM = wid & 1, warpN = wid >> 1;
    const int lm = lane >> 3, lr = lane & 7;

    const float* Ab = A + (size_t)(blockIdx.y * 128) * K;
    const float* Bb = Bt + (size_t)(blockIdx.x * 128) * K;

    int rowu[4], colu[4];
    #pragma unroll
    for (int u = 0; u < 4; u++) {
        int idx = tid + u * 256;
        rowu[u] = idx >> 3;  colu[u] = (idx & 7) * 4;
    }
    uint32_t a_dst[4], b_dst[4];
    #pragma unroll
    for (int u = 0; u < 4; u++) {
        a_dst[u] = (rowu[u] * TS + colu[u]) * 4;
        b_dst[u] = ((128 + rowu[u]) * TS + colu[u]) * 4;
    }

    const uint32_t aoff = (uint32_t)((((lm & 1) * 8 + lr) * TS + (lm >> 1) * 4) * 4);
    const uint32_t boff = (uint32_t)((((lm >> 1) * 8 + lr) * TS + (lm & 1) * 4) * 4);
    const uint32_t a_base0 = (uint32_t)(warpM * 64 * TS * 4) + aoff;
    const uint32_t b_base0 = (uint32_t)((128 + warpN * 32) * TS * 4) + boff;

    float acc[4][4][4];
    #pragma unroll
    for (int mi = 0; mi < 4; mi++)
        #pragma unroll
        for (int ni = 0; ni < 4; ni++)
            #pragma unroll
            for (int e = 0; e < 4; e++) acc[mi][ni][e] = 0.f;

    const int ktiles = K >> 5;

    auto issue = [&](int kt, int s) {
        const int k0 = kt << 5;
        const uint32_t sb = sm_base + s * STAGE_BYTES;
        #pragma unroll
        for (int u = 0; u < 4; u++)
            cp_async16(sb + a_dst[u], Ab + (size_t)rowu[u] * K + k0 + colu[u]);
        #pragma unroll
        for (int u = 0; u < 4; u++)
            cp_async16(sb + b_dst[u], Bb + (size_t)rowu[u] * K + k0 + colu[u]);
    };

    issue(0, 0); CP_COMMIT();
    issue(1, 1); CP_COMMIT();

    int s_cur = 0;
    for (int kt = 0; kt < ktiles; kt++) {
        CP_WAIT1();
        __syncthreads();

        if (kt + 2 < ktiles) {
            int s_next = s_cur + 2; if (s_next >= 3) s_next -= 3;
            issue(kt + 2, s_next);
        }
        CP_COMMIT();

        const uint32_t aA = sm_base + s_cur * STAGE_BYTES + a_base0;
        const uint32_t aB = sm_base + s_cur * STAGE_BYTES + b_base0;
        #pragma unroll
        for (int ks = 0; ks < 4; ks++) {
            const uint32_t kb4 = ks * 8 * 4;
            uint32_t af[4][4], bf[4][2];
            #pragma unroll
            for (int mi = 0; mi < 4; mi++)
                ldm_x4(af[mi], aA + mi * (16 * TS * 4) + kb4);
            #pragma unroll
            for (int np = 0; np < 2; np++) {
                uint32_t tmp[4];
                ldm_x4(tmp, aB + np * (16 * TS * 4) + kb4);
                bf[np * 2][0] = tmp[0];     bf[np * 2][1] = tmp[1];
                bf[np * 2 + 1][0] = tmp[2]; bf[np * 2 + 1][1] = tmp[3];
            }
            #pragma unroll
            for (int mi = 0; mi < 4; mi++)
                #pragma unroll
                for (int ni = 0; ni < 4; ni++)
                    MMA_TF32(acc[mi][ni], af[mi], bf[ni]);
        }

        s_cur++; if (s_cur >= 3) s_cur = 0;
    }

    if (mode == 0) {
        #pragma unroll
        for (int mi = 0; mi < 4; mi++) {
            const int row = blockIdx.y * 128 + warpM * 64 + mi * 16 + g;
            #pragma unroll
            for (int ni = 0; ni < 4; ni++) {
                const int col = blockIdx.x * 128 + warpN * 32 + ni * 8 + t * 2;
                const float b0 = bias[col], b1 = bias[col + 1];
                float2 v0 = make_float2(acc[mi][ni][0] + b0, acc[mi][ni][1] + b1);
                float2 v1 = make_float2(acc[mi][ni][2] + b0, acc[mi][ni][3] + b1);
                *(float2*)(C + (size_t)row * N + col)       = v0;
                *(float2*)(C + (size_t)(row + 8) * N + col) = v1;
            }
        }
    } else {
        // QKV scatter epilogue. col -> type (0=Q,1=K,2=V), head, d.
        const float QSC = 0.125f * 1.4426950408889634f;
        const int colbase = blockIdx.x * 128 + warpN * 32;
        #pragma unroll
        for (int mi = 0; mi < 4; mi++) {
            const int row = blockIdx.y * 128 + warpM * 64 + mi * 16 + g;
            const int bb = row >> 11, ss = row & (SS - 1);
            #pragma unroll
            for (int ni = 0; ni < 4; ni++) {
                const int col = colbase + ni * 8 + t * 2;
                const float b0 = bias[col], b1 = bias[col + 1];
                const float v00 = acc[mi][ni][0] + b0, v01 = acc[mi][ni][1] + b1;
                const float v10 = acc[mi][ni][2] + b0, v11 = acc[mi][ni][3] + b1;
                const int type = col >> 10;      // uniform per CTA
                const int cin = col & 1023;
                if (type == 0) {
                    float* dst = C + ((size_t)(bb * SS + ss)) * NXC + cin;
                    *(uint2*)dst = make_uint2(f2tf32(v00 * QSC), f2tf32(v01 * QSC));
                    *(uint2*)(dst + 8 * NXC) =
                        make_uint2(f2tf32(v10 * QSC), f2tf32(v11 * QSC));
                } else {
                    const int hh2 = cin >> 6, dd = cin & 63;
                    const size_t base =
                        ((((size_t)(type - 1) * BB + bb) * HH + hh2) * TLEN
                         + PPC + ss) * DDC + dd;
                    *(float2*)(present + base) = make_float2(v00, v01);
                    *(float2*)(present + base + 8 * DDC) = make_float2(v10, v11);
                    *(uint2*)(kvr + base) = make_uint2(f2tf32(v00), f2tf32(v01));
                    *(uint2*)(kvr + base + 8 * DDC) = make_uint2(f2tf32(v10), f2tf32(v11));
                }
            }
        }
    }
}

// ---------------------------------------------------------------------------
// Flash attention (R15 structure): 64q/CTA, 128 thr, 2 CTAs/SM, no-max
// softmax (MUFU), LPT, warp-private P, 1 barrier/tile. Q read pre-scaled
// pre-rounded from g_qr (plain copy, no cvt).
// ---------------------------------------------------------------------------
#define Q_OFF 0          // 64*68  = 4352
#define K_OFF 4352       // 2*64*68 = 8704
#define V_OFF 13056      // 2*64*72 = 9216
#define P_OFF 22272      // 4 warps * 32*36 = 4608
#define SX_OFF 26880     // 128
#define ATTN_SMEM (27008 * 4)   // 108032 bytes -> 2 CTAs/SM

__global__ __launch_bounds__(128, 2)
void attn_mma_kernel(const float* __restrict__ kvr, const float* __restrict__ qr)
{
    extern __shared__ float smf[];
    uint32_t sm_base;
    asm("{ .reg .u64 t; cvta.to.shared.u64 t, %1; cvt.u32.u64 %0, t; }"
        : "=r"(sm_base) : "l"(smf));

    const int qb = gridDim.x - 1 - blockIdx.x;   // LPT: biggest jobs first
    const int h = blockIdx.y, b = blockIdx.z;
    const int tid = threadIdx.x, wid = tid >> 5, lane = tid & 31;
    const int g = lane >> 2, t = lane & 3;
    const int wq = wid >> 1, wk = wid & 1;
    const int rA = wq * 32 + g;
    const int lm = lane >> 3, lr = lane & 7;

    const float* Kb = kvr + (size_t)(b * HH + h) * TLEN * DDC;
    const float* Vb = Kb + (size_t)BB * HH * TLEN * DDC;

    const int lrow = tid >> 4, lc4 = (tid & 15) << 2;
    {
        const float* src = qr + ((size_t)(b * SS + qb * 64 + lrow)) * NXC
                         + h * DDC + lc4;
        float* dq = smf + Q_OFF + lrow * 68 + lc4;
        #pragma unroll
        for (int u = 0; u < 8; u++)
            *(uint4*)(dq + u * 8 * 68) = *(const uint4*)(src + (size_t)u * 8 * NXC);
    }

    const uint32_t aoff68 = (uint32_t)((((lm & 1) * 8 + lr) * 68 + (lm >> 1) * 4) * 4);
    const uint32_t aoff36 = (uint32_t)((((lm & 1) * 8 + lr) * 36 + (lm >> 1) * 4) * 4);
    const uint32_t boff68 = (uint32_t)((((lm >> 1) * 8 + lr) * 68 + (lm & 1) * 4) * 4);

    const uint32_t aQ  = sm_base + Q_OFF * 4 + (uint32_t)(wq * 32 * 68 * 4) + aoff68;
    const uint32_t aP  = sm_base + P_OFF * 4 + (uint32_t)(wid * 1152 * 4) + aoff36;
    const uint32_t bK0 = sm_base + K_OFF * 4 + (uint32_t)(wk * 32 * 68 * 4) + boff68;
    float* Pw = smf + P_OFF + wid * 1152;   // warp-private 32x36

    float o[2][8][4];
    #pragma unroll
    for (int mi = 0; mi < 2; mi++)
        #pragma unroll
        for (int ni = 0; ni < 8; ni++)
            #pragma unroll
            for (int e = 0; e < 4; e++) o[mi][ni][e] = 0.f;
    float l[2][2] = {{0.f, 0.f}, {0.f, 0.f}};

    const uint32_t kdst0 = sm_base + (K_OFF + lrow * 68 + lc4) * 4;
    const uint32_t vdst0 = sm_base + (V_OFF + lrow * 72 + lc4) * 4;
    const float* ksrc0 = Kb + lrow * DDC + lc4;
    const float* vsrc0 = Vb + lrow * DDC + lc4;

    auto issue = [&](int kt, int s) {
        const size_t off = (size_t)kt * 64 * DDC;
        const uint32_t kd = kdst0 + s * 4352 * 4;
        const uint32_t vd = vdst0 + s * 4608 * 4;
        #pragma unroll
        for (int u = 0; u < 8; u++) {
            cp_async16(kd + u * 8 * 68 * 4, ksrc0 + off + u * 8 * DDC);
            cp_async16(vd + u * 8 * 72 * 4, vsrc0 + off + u * 8 * DDC);
        }
    };

    const int ntiles = qb + 9;
    issue(0, 0); CP_COMMIT();

    for (int kt = 0; kt < ntiles; kt++) {
        CP_WAIT0();
        __syncthreads();
        if (kt + 1 < ntiles) { issue(kt + 1, (kt + 1) & 1); CP_COMMIT(); }

        const uint32_t bK = bK0 + (uint32_t)((kt & 1) * 4352 * 4);
        const uint32_t* Vu = (const uint32_t*)(smf + V_OFF + (kt & 1) * 4608);

        float s[2][4][4];
        #pragma unroll
        for (int mi = 0; mi < 2; mi++)
            #pragma unroll
            for (int ni = 0; ni < 4; ni++)
                #pragma unroll
                for (int e = 0; e < 4; e++) s[mi][ni][e] = 0.f;

        #pragma unroll
        for (int ks = 0; ks < 8; ks++) {
            const uint32_t kb4 = ks * 8 * 4;
            uint32_t af[2][4], bf[4][2];
            #pragma unroll
            for (int mi = 0; mi < 2; mi++)
                ldm_x4(af[mi], aQ + mi * (16 * 68 * 4) + kb4);
            #pragma unroll
            for (int np = 0; np < 2; np++) {
                uint32_t tmp[4];
                ldm_x4(tmp, bK + np * (16 * 68 * 4) + kb4);
                bf[np * 2][0] = tmp[0];     bf[np * 2][1] = tmp[1];
                bf[np * 2 + 1][0] = tmp[2]; bf[np * 2 + 1][1] = tmp[3];
            }
            #pragma unroll
            for (int mi = 0; mi < 2; mi++)
                #pragma unroll
                for (int ni = 0; ni < 4; ni++)
                    MMA_TF32(s[mi][ni], af[mi], bf[ni]);
        }

        if (kt == ntiles - 1) {
            #pragma unroll
            for (int mi = 0; mi < 2; mi++) {
                const int r = rA + mi * 16;
                #pragma unroll
                for (int ni = 0; ni < 4; ni++) {
                    const int c = wk * 32 + ni * 8 + 2 * t;
                    if (c     > r)     s[mi][ni][0] = -1e30f;
                    if (c + 1 > r)     s[mi][ni][1] = -1e30f;
                    if (c     > r + 8) s[mi][ni][2] = -1e30f;
                    if (c + 1 > r + 8) s[mi][ni][3] = -1e30f;
                }
            }
        }

        #pragma unroll
        for (int mi = 0; mi < 2; mi++) {
            const int rl = g + mi * 16;
            #pragma unroll
            for (int ni = 0; ni < 4; ni++) {
                const float e0 = ex2f(s[mi][ni][0]);
                const float e1 = ex2f(s[mi][ni][1]);
                const float e2 = ex2f(s[mi][ni][2]);
                const float e3 = ex2f(s[mi][ni][3]);
                l[mi][0] += e0 + e1;
                l[mi][1] += e2 + e3;
                const int c = ni * 8 + 2 * t;
                *(uint2*)&Pw[rl * 36 + c]       = make_uint2(f2tf32(e0), f2tf32(e1));
                *(uint2*)&Pw[(rl + 8) * 36 + c] = make_uint2(f2tf32(e2), f2tf32(e3));
            }
        }
        __syncwarp();

        #pragma unroll
        for (int ks = 0; ks < 4; ks++) {
            const int kb = wk * 32 + ks * 8;
            uint32_t af[2][4], bf[8][2];
            #pragma unroll
            for (int mi = 0; mi < 2; mi++)
                ldm_x4(af[mi], aP + mi * (16 * 36 * 4) + ks * 8 * 4);
            #pragma unroll
            for (int ni = 0; ni < 8; ni++) {
                const int c0 = ni * 8 + g;
                bf[ni][0] = Vu[(kb + t) * 72 + c0];
                bf[ni][1] = Vu[(kb + t + 4) * 72 + c0];
            }
            #pragma unroll
            for (int mi = 0; mi < 2; mi++)
                #pragma unroll
                for (int ni = 0; ni < 8; ni++)
                    MMA_TF32(o[mi][ni], af[mi], bf[ni]);
        }
    }

    float* Sx = smf + SX_OFF;
    #pragma unroll
    for (int mi = 0; mi < 2; mi++)
        #pragma unroll
        for (int hh = 0; hh < 2; hh++) {
            float v = l[mi][hh];
            v += __shfl_xor_sync(0xffffffffu, v, 1);
            v += __shfl_xor_sync(0xffffffffu, v, 2);
            l[mi][hh] = v;
        }
    if (t == 0) {
        #pragma unroll
        for (int mi = 0; mi < 2; mi++) {
            Sx[wk * 64 + rA + mi * 16]     = l[mi][0];
            Sx[wk * 64 + rA + mi * 16 + 8] = l[mi][1];
        }
    }

    float* Ox = smf + K_OFF;
    if (wk == 1) {
        #pragma unroll
        for (int mi = 0; mi < 2; mi++) {
            const int r = rA + mi * 16;
            #pragma unroll
            for (int ni = 0; ni < 8; ni++) {
                const int c = ni * 8 + 2 * t;
                *(float2*)&Ox[r * 68 + c]       = make_float2(o[mi][ni][0], o[mi][ni][1]);
                *(float2*)&Ox[(r + 8) * 68 + c] = make_float2(o[mi][ni][2], o[mi][ni][3]);
            }
        }
    }
    __syncthreads();

    if (wk == 0) {
        #pragma unroll
        for (int mi = 0; mi < 2; mi++) {
            const int row0 = rA + mi * 16;
            const float inv0 = rcpf(Sx[row0] + Sx[64 + row0]);
            const float inv1 = rcpf(Sx[row0 + 8] + Sx[64 + row0 + 8]);
            const int srow = qb * 64 + row0;
            float* dst0 = g_attn + ((size_t)(b * SS + srow)) * NXC + h * DDC;
            float* dst1 = dst0 + (size_t)8 * NXC;
            #pragma unroll
            for (int ni = 0; ni < 8; ni++) {
                const int c = ni * 8 + 2 * t;
                float2 p0 = *(float2*)&Ox[row0 * 68 + c];
                float2 p1 = *(float2*)&Ox[(row0 + 8) * 68 + c];
                *(uint2*)(dst0 + c) = make_uint2(f2tf32((o[mi][ni][0] + p0.x) * inv0),
                                                 f2tf32((o[mi][ni][1] + p0.y) * inv0));
                *(uint2*)(dst1 + c) = make_uint2(f2tf32((o[mi][ni][2] + p1.x) * inv1),
                                                 f2tf32((o[mi][ni][3] + p1.y) * inv1));
            }
        }
    }
}

// ---------------------------------------------------------------------------
extern "C" void kernel_launch(void* const* d_in, const int* in_sizes, int n_in,
                              void* d_out, int out_size)
{
    const float* x     = (const float*)d_in[0];
    const float* past  = (const float*)d_in[1];
    const float* wqkv  = (const float*)d_in[2];
    const float* bqkv  = (const float*)d_in[3];
    const float* wproj = (const float*)d_in[4];
    const float* bproj = (const float*)d_in[5];
    float* out = (float*)d_out;

    float *qr, *attn, *kvr, *xr, *wqkvt, *wprojt;
    cudaGetSymbolAddress((void**)&qr, g_qr);
    cudaGetSymbolAddress((void**)&attn, g_attn);
    cudaGetSymbolAddress((void**)&kvr, g_kvr);
    cudaGetSymbolAddress((void**)&xr, g_xr);
    cudaGetSymbolAddress((void**)&wqkvt, g_wqkvt);
    cudaGetSymbolAddress((void**)&wprojt, g_wprojt);

    float* present = nullptr;
    if ((long long)out_size >= A_SIZE + 2 * PH) {
        present = out + A_SIZE;
    } else {
        cudaGetSymbolAddress((void**)&present, g_present_fb);
    }

    cudaFuncSetAttribute(gemm_tf32_kernel,
                         cudaFuncAttributeMaxDynamicSharedMemorySize, GEMM_SMEM);
    cudaFuncSetAttribute(attn_mma_kernel,
                         cudaFuncAttributeMaxDynamicSharedMemorySize, ATTN_SMEM);

    // 0) pre-round x; transpose+round weights; past -> present/kvr
    round_tf32_kernel<<<(int)(A_SIZE / 4 / 256), 256>>>(x, xr);
    trans_round_kernel<<<dim3(3 * NXC / 32, NXC / 32), 256>>>(wqkv, wqkvt, NXC, 3 * NXC);
    trans_round_kernel<<<dim3(NXC / 32, NXC / 32), 256>>>(wproj, wprojt, NXC, NXC);
    {
        long long tot = 2LL * BB * HH * (PPC * DDC / 4);
        build_past_kernel<<<(int)((tot + 255) / 256), 256>>>(past, present, kvr);
    }

    // 1) QKV GEMM with fused scatter epilogue (Q->qr, K/V->present+kvr)
    gemm_tf32_kernel<<<dim3(3 * NXC / 128, BB * SS / 128), 256, GEMM_SMEM>>>(
        xr, wqkvt, bqkv, qr, BB * SS, 3 * NXC, NXC, 1, present, kvr);

    // 2) flash attention
    attn_mma_kernel<<<dim3(SS / 64, HH, BB), 128, ATTN_SMEM>>>(kvr, qr);

    // 3) output projection
    gemm_tf32_kernel<<<dim3(NXC / 128, BB * SS / 128), 256, GEMM_SMEM>>>(
        attn, wprojt, bproj, out, BB * SS, NXC, NXC, 0, nullptr, nullptr);
}